// round 13
// baseline (speedup 1.0000x reference)
#include <cuda_runtime.h>
#include <cstdint>

#define NMAX 100000
#define EMAX 1600000
#define MAXD 64   // static bucket capacity; P(Poisson(16) > 64) ~ 1e-18

// scratch (static device globals — no allocation allowed)
__device__ float  g_src2[NMAX * 32];
__device__ float  g_dst2[NMAX * 32];
__device__ int    g_cur[NMAX];          // per-dst cursor == in-degree (zeroed by k_out)
__device__ int    g_bkt[NMAX * MAXD];   // src ids bucketed by dst
__device__ float4 g_Xk[16 * NMAX];      // K-MAJOR: [kq][node], kq<8: F, kq>=8: deg*fv
__device__ float  g_degf[NMAX];
__device__ float  g_W[64 * 64];         // W[k][o]: combined A1/A2/B1/B2 (k=in, o=out)
__device__ float4 g_b1v[16], g_b2v[16]; // bias: y[o] += deg*b1[o] + b2[o]

__device__ __forceinline__ void cp_async16(unsigned sa, const void* gptr) {
    asm volatile("cp.async.cg.shared.global [%0], [%1], 16;" :: "r"(sa), "l"(gptr));
}

// W0: compose weights (single block).
__global__ void k_weights(const float* __restrict__ Ws, const float* __restrict__ Wd,
                          const float* __restrict__ bd, const float* __restrict__ Wr,
                          const float* __restrict__ br)
{
    __shared__ float sWs[1024], sWd[1024], sWr[1024], sP[1024], sQ[1024];
    __shared__ float sp[32];
    int t = threadIdx.x;
    for (int i = t; i < 1024; i += 256) {
        sWs[i] = Ws[i]; sWd[i] = Wd[i]; sWr[i] = Wr[i];
    }
    __syncthreads();
    for (int i = t; i < 1024; i += 256) {
        int r = i >> 5, c = i & 31;
        float accP = 0.f, accQ = 0.f;
        #pragma unroll
        for (int k = 0; k < 32; k++) {
            float w = sWr[r * 32 + k];
            accP += w * sWs[k * 32 + c];
            accQ += w * sWd[k * 32 + c];
        }
        sP[i] = accP; sQ[i] = accQ;
    }
    if (t < 32) {
        float acc = 0.f;
        #pragma unroll
        for (int k = 0; k < 32; k++) acc += sWr[t * 32 + k] * bd[k];
        sp[t] = acc;
    }
    __syncthreads();
    for (int i = t; i < 1024; i += 256) {
        int r = i >> 5, c = i & 31;
        float a1 = 0.f, a2 = 0.f, b1 = 0.f, b2 = 0.f;
        #pragma unroll
        for (int k = 0; k < 32; k++) {
            float ws = sWs[r * 32 + k], wd = sWd[r * 32 + k];
            float pk = sP[k * 32 + c], qk = sQ[k * 32 + c];
            a1 += ws * pk; a2 += ws * qk;
            b1 += wd * pk; b2 += wd * qk;
        }
        g_W[c * 64 + r]               = a1;
        g_W[(c + 32) * 64 + r]        = a2;
        g_W[c * 64 + (r + 32)]        = b1;
        g_W[(c + 32) * 64 + (r + 32)] = b2;
    }
    if (t < 32) {
        float c1 = 0.f, c2 = 0.f, d1 = 0.f, d2 = 0.f;
        #pragma unroll
        for (int k = 0; k < 32; k++) {
            float ws = sWs[t * 32 + k], wd = sWd[t * 32 + k];
            c1 += ws * sp[k];  c2 += ws * br[k];
            d1 += wd * sp[k];  d2 += wd * br[k];
        }
        float* b1p = (float*)g_b1v;
        float* b2p = (float*)g_b2v;
        b1p[t] = c1;       b2p[t] = c2;
        b1p[t + 32] = d1;  b2p[t + 32] = d2 + bd[t];
    }
}

// W1: bucket build, 4 edges/thread via int4
__global__ void __launch_bounds__(256) k_build(const int* __restrict__ src,
                                               const int* __restrict__ dst, int E)
{
    int q = blockIdx.x * blockDim.x + threadIdx.x;
    int e0 = q * 4;
    if (e0 + 3 < E) {
        int4 s4 = __ldg((const int4*)(src) + q);
        int4 d4 = __ldg((const int4*)(dst) + q);
        int p;
        p = atomicAdd(&g_cur[d4.x], 1); if (p < MAXD) g_bkt[d4.x * MAXD + p] = s4.x;
        p = atomicAdd(&g_cur[d4.y], 1); if (p < MAXD) g_bkt[d4.y * MAXD + p] = s4.y;
        p = atomicAdd(&g_cur[d4.z], 1); if (p < MAXD) g_bkt[d4.z * MAXD + p] = s4.z;
        p = atomicAdd(&g_cur[d4.w], 1); if (p < MAXD) g_bkt[d4.w * MAXD + p] = s4.w;
    } else {
        for (int e = e0; e < E; e++) {
            int d = __ldg(&dst[e]);
            int p = atomicAdd(&g_cur[d], 1);
            if (p < MAXD) g_bkt[d * MAXD + p] = __ldg(&src[e]);
        }
    }
}

// W2: warp per node, float4-vectorized gather, 32 edges in flight (8 loads/lane).
// Writes X k-major: g_Xk[kq*NMAX + node].
__global__ void k_gather(const float* __restrict__ feat, int N)
{
    int t = threadIdx.x, lane = t & 31, w = t >> 5;
    int node = blockIdx.x * 8 + w;
    if (node >= N) return;
    int cnt = min(__ldg(&g_cur[node]), MAXD);
    int sub = lane >> 3;
    int ch  = lane & 7;

    float4 acc = make_float4(0.f, 0.f, 0.f, 0.f);
    const int* bkt = &g_bkt[node * MAXD];
    for (int base = 0; base < cnt; base += 32) {
        int i = base + sub;
        int s[8];
        #pragma unroll
        for (int k = 0; k < 8; k++)
            s[k] = (i + 4 * k < cnt) ? __ldg(&bkt[i + 4 * k]) : -1;
        #pragma unroll
        for (int k = 0; k < 8; k++) {
            if (s[k] >= 0) {
                float4 v = __ldg(reinterpret_cast<const float4*>(&feat[s[k] * 32]) + ch);
                acc.x += v.x; acc.y += v.y; acc.z += v.z; acc.w += v.w;
            }
        }
    }
    #pragma unroll
    for (int off = 16; off >= 8; off >>= 1) {
        acc.x += __shfl_xor_sync(0xffffffffu, acc.x, off);
        acc.y += __shfl_xor_sync(0xffffffffu, acc.y, off);
        acc.z += __shfl_xor_sync(0xffffffffu, acc.z, off);
        acc.w += __shfl_xor_sync(0xffffffffu, acc.w, off);
    }
    float degf = (float)cnt;
    if (lane < 8) {
        g_Xk[ch * NMAX + node] = acc;                     // F chunk, k-major
    } else if (lane < 16) {
        float4 fv = __ldg(reinterpret_cast<const float4*>(&feat[node * 32]) + ch);
        g_Xk[(8 + ch) * NMAX + node] = make_float4(degf * fv.x, degf * fv.y,
                                                   degf * fv.z, degf * fv.w);
    }
    if (lane == 0) g_degf[node] = degf;
}

// W3: persistent double-buffered GEMM: per 128-node tile, Y = X·W + deg*b1 + b2.
// 128 threads; thread = (tx 0..7 -> 8 outs, ty 0..15 -> nodes ty+n*16).
// cp.async prefetch of next tile's X overlaps current tile's FMA.
// sW conflict-free layout: even o-quads in slots 0..7, odd in 8..15.
__global__ void __launch_bounds__(128) k_gemm(int N, int numTiles)
{
    extern __shared__ float4 smem[];
    float4* sX0 = smem;            // 2048
    float4* sX1 = smem + 2048;     // 2048
    float4* sW  = smem + 4096;     // 1024
    int t = threadIdx.x;

    for (int i = t; i < 1024; i += 128) {
        int r = i >> 4, slot = i & 15;
        int oq = (slot < 8) ? (2 * slot) : (2 * (slot - 8) + 1);
        sW[i] = __ldg(&((const float4*)g_W)[r * 16 + oq]);
    }

    int tx = t & 7, ty = t >> 3;
    float4 b1a = __ldg(&g_b1v[tx * 2]), b1b = __ldg(&g_b1v[tx * 2 + 1]);
    float4 b2a = __ldg(&g_b2v[tx * 2]), b2b = __ldg(&g_b2v[tx * 2 + 1]);
    int o = tx * 8;

    // prefetch first tile
    int tile = blockIdx.x;
    if (tile < numTiles) {
        int base = tile * 128;
        #pragma unroll
        for (int i = 0; i < 16; i++) {
            int idx = t + i * 128;
            int kq = idx >> 7, n = idx & 127;
            int node = base + n;
            if (node < N)
                cp_async16((unsigned)__cvta_generic_to_shared(&sX0[idx]),
                           &g_Xk[kq * NMAX + node]);
            else
                sX0[idx] = make_float4(0.f, 0.f, 0.f, 0.f);
        }
        asm volatile("cp.async.commit_group;");
    }

    int buf = 0;
    for (; tile < numTiles; tile += gridDim.x) {
        asm volatile("cp.async.wait_group 0;");
        __syncthreads();   // current tile ready; all warps done with prev compute

        int nxt = tile + gridDim.x;
        float4* sXn = buf ? sX0 : sX1;
        if (nxt < numTiles) {
            int nbase = nxt * 128;
            #pragma unroll
            for (int i = 0; i < 16; i++) {
                int idx = t + i * 128;
                int kq = idx >> 7, n = idx & 127;
                int node = nbase + n;
                if (node < N)
                    cp_async16((unsigned)__cvta_generic_to_shared(&sXn[idx]),
                               &g_Xk[kq * NMAX + node]);
                else
                    sXn[idx] = make_float4(0.f, 0.f, 0.f, 0.f);
            }
            asm volatile("cp.async.commit_group;");
        }

        const float4* sX = buf ? sX1 : sX0;
        int base = tile * 128;

        float4 acc[8][2];
        #pragma unroll
        for (int n = 0; n < 8; n++) {
            acc[n][0] = make_float4(0.f, 0.f, 0.f, 0.f);
            acc[n][1] = make_float4(0.f, 0.f, 0.f, 0.f);
        }

        #pragma unroll
        for (int kk = 0; kk < 16; kk++) {
            float4 w0[4], w1[4];
            #pragma unroll
            for (int k4 = 0; k4 < 4; k4++) {
                int row = kk * 4 + k4;
                w0[k4] = sW[row * 16 + tx];       // conflict-free (128B-contiguous)
                w1[k4] = sW[row * 16 + 8 + tx];
            }
            #pragma unroll
            for (int n = 0; n < 8; n++) {
                float4 xv = sX[kk * 128 + ty + n * 16];
                float xs;
                #define FMA8(K4, XS) \
                    acc[n][0].x += (XS) * w0[K4].x; acc[n][0].y += (XS) * w0[K4].y; \
                    acc[n][0].z += (XS) * w0[K4].z; acc[n][0].w += (XS) * w0[K4].w; \
                    acc[n][1].x += (XS) * w1[K4].x; acc[n][1].y += (XS) * w1[K4].y; \
                    acc[n][1].z += (XS) * w1[K4].z; acc[n][1].w += (XS) * w1[K4].w;
                xs = xv.x; FMA8(0, xs);
                xs = xv.y; FMA8(1, xs);
                xs = xv.z; FMA8(2, xs);
                xs = xv.w; FMA8(3, xs);
                #undef FMA8
            }
        }

        #pragma unroll
        for (int n = 0; n < 8; n++) {
            int node = base + ty + n * 16;
            if (node >= N) continue;
            float dg = __ldg(&g_degf[node]);
            float4 y0 = make_float4(acc[n][0].x + dg * b1a.x + b2a.x,
                                    acc[n][0].y + dg * b1a.y + b2a.y,
                                    acc[n][0].z + dg * b1a.z + b2a.z,
                                    acc[n][0].w + dg * b1a.w + b2a.w);
            float4 y1 = make_float4(acc[n][1].x + dg * b1b.x + b2b.x,
                                    acc[n][1].y + dg * b1b.y + b2b.y,
                                    acc[n][1].z + dg * b1b.z + b2b.z,
                                    acc[n][1].w + dg * b1b.w + b2b.w);
            float* dstp = (o < 32) ? &g_src2[node * 32 + o] : &g_dst2[node * 32 + (o - 32)];
            ((float4*)dstp)[0] = y0;
            ((float4*)dstp)[1] = y1;
        }
        buf ^= 1;
    }
}

// W4: 4 threads/edge, 2 float4 each; idx loaded once per 4-lane group, shfl-broadcast.
// Also re-zeroes g_cur for the next launch (stream-ordered after k_gather).
__global__ void k_out(const int* __restrict__ src, const int* __restrict__ dst,
                      float4* __restrict__ out, int E, int N)
{
    int gt = blockIdx.x * blockDim.x + threadIdx.x;
    if (gt < N) g_cur[gt] = 0;
    if (gt >= E * 4) return;
    int e = gt >> 2;
    int lane = threadIdx.x & 31;
    int q = lane & 3;
    int s = 0, d = 0;
    if (q == 0) { s = __ldg(&src[e]); d = __ldg(&dst[e]); }
    s = __shfl_sync(0xffffffffu, s, lane & 28);
    d = __shfl_sync(0xffffffffu, d, lane & 28);
    const float4* ps = reinterpret_cast<const float4*>(&g_src2[s * 32]) + q * 2;
    const float4* pd = reinterpret_cast<const float4*>(&g_dst2[d * 32]) + q * 2;
    float4 a0 = __ldg(ps), a1 = __ldg(ps + 1);
    float4 b0 = __ldg(pd), b1 = __ldg(pd + 1);
    out[e * 8 + q * 2]     = make_float4(a0.x + b0.x, a0.y + b0.y, a0.z + b0.z, a0.w + b0.w);
    out[e * 8 + q * 2 + 1] = make_float4(a1.x + b1.x, a1.y + b1.y, a1.z + b1.z, a1.w + b1.w);
}

extern "C" void kernel_launch(void* const* d_in, const int* in_sizes, int n_in,
                              void* d_out, int out_size)
{
    const float* feat = (const float*)d_in[0];
    const int*   src  = (const int*)d_in[1];
    const int*   dst  = (const int*)d_in[2];
    const float* Ws   = (const float*)d_in[3];
    const float* Wd   = (const float*)d_in[4];
    const float* bd   = (const float*)d_in[5];
    const float* Wr   = (const float*)d_in[6];
    const float* br   = (const float*)d_in[7];

    int N = in_sizes[0] / 32;
    int E = in_sizes[1];

    k_weights<<<1, 256>>>(Ws, Wd, bd, Wr, br);

    int buildBlocks = (E + 1023) / 1024;
    k_build<<<buildBlocks, 256>>>(src, dst, E);

    int gatherBlocks = (N + 7) / 8;
    k_gather<<<gatherBlocks, 256>>>(feat, N);

    int numTiles = (N + 127) / 128;
    int gemmBlocks = numTiles < 296 ? numTiles : 296;   // persistent, 2 blocks/SM
    size_t shbytes = (size_t)(4096 + 1024) * sizeof(float4);   // 80 KB
    cudaFuncSetAttribute(k_gemm, cudaFuncAttributeMaxDynamicSharedMemorySize, (int)shbytes);
    k_gemm<<<gemmBlocks, 128, shbytes>>>(N, numTiles);

    int outBlocks = (E * 4 + 255) / 256;
    k_out<<<outBlocks, 256>>>(src, dst, (float4*)d_out, E, N);
}

// round 14
// speedup vs baseline: 1.0154x; 1.0154x over previous
#include <cuda_runtime.h>
#include <cstdint>

#define NMAX 100000
#define EMAX 1600000
#define MAXD 64   // static bucket capacity; P(Poisson(16) > 64) ~ 1e-18

// scratch (static device globals — no allocation allowed)
__device__ float  g_src2[NMAX * 32];
__device__ float  g_dst2[NMAX * 32];
__device__ int    g_cur[NMAX];          // per-dst cursor == in-degree (zeroed by k_out)
__device__ int    g_bkt[NMAX * MAXD];   // src ids bucketed by dst
__device__ float4 g_Xk[16 * NMAX];      // K-MAJOR: [kq][node], kq<8: F, kq>=8: deg*fv
__device__ float  g_degf[NMAX];
__device__ float  g_W[64 * 64];         // W[k][o]: combined A1/A2/B1/B2 (k=in, o=out)
__device__ float4 g_b1v[16], g_b2v[16]; // bias: y[o] += deg*b1[o] + b2[o]

// W0: compose weights (single block).
__global__ void k_weights(const float* __restrict__ Ws, const float* __restrict__ Wd,
                          const float* __restrict__ bd, const float* __restrict__ Wr,
                          const float* __restrict__ br)
{
    __shared__ float sWs[1024], sWd[1024], sWr[1024], sP[1024], sQ[1024];
    __shared__ float sp[32];
    int t = threadIdx.x;
    for (int i = t; i < 1024; i += 256) {
        sWs[i] = Ws[i]; sWd[i] = Wd[i]; sWr[i] = Wr[i];
    }
    __syncthreads();
    for (int i = t; i < 1024; i += 256) {
        int r = i >> 5, c = i & 31;
        float accP = 0.f, accQ = 0.f;
        #pragma unroll
        for (int k = 0; k < 32; k++) {
            float w = sWr[r * 32 + k];
            accP += w * sWs[k * 32 + c];
            accQ += w * sWd[k * 32 + c];
        }
        sP[i] = accP; sQ[i] = accQ;
    }
    if (t < 32) {
        float acc = 0.f;
        #pragma unroll
        for (int k = 0; k < 32; k++) acc += sWr[t * 32 + k] * bd[k];
        sp[t] = acc;
    }
    __syncthreads();
    for (int i = t; i < 1024; i += 256) {
        int r = i >> 5, c = i & 31;
        float a1 = 0.f, a2 = 0.f, b1 = 0.f, b2 = 0.f;
        #pragma unroll
        for (int k = 0; k < 32; k++) {
            float ws = sWs[r * 32 + k], wd = sWd[r * 32 + k];
            float pk = sP[k * 32 + c], qk = sQ[k * 32 + c];
            a1 += ws * pk; a2 += ws * qk;
            b1 += wd * pk; b2 += wd * qk;
        }
        g_W[c * 64 + r]               = a1;
        g_W[(c + 32) * 64 + r]        = a2;
        g_W[c * 64 + (r + 32)]        = b1;
        g_W[(c + 32) * 64 + (r + 32)] = b2;
    }
    if (t < 32) {
        float c1 = 0.f, c2 = 0.f, d1 = 0.f, d2 = 0.f;
        #pragma unroll
        for (int k = 0; k < 32; k++) {
            float ws = sWs[t * 32 + k], wd = sWd[t * 32 + k];
            c1 += ws * sp[k];  c2 += ws * br[k];
            d1 += wd * sp[k];  d2 += wd * br[k];
        }
        float* b1p = (float*)g_b1v;
        float* b2p = (float*)g_b2v;
        b1p[t] = c1;       b2p[t] = c2;
        b1p[t + 32] = d1;  b2p[t + 32] = d2 + bd[t];
    }
}

// W1: bucket build, 4 edges/thread via int4
__global__ void __launch_bounds__(256) k_build(const int* __restrict__ src,
                                               const int* __restrict__ dst, int E)
{
    int q = blockIdx.x * blockDim.x + threadIdx.x;
    int e0 = q * 4;
    if (e0 + 3 < E) {
        int4 s4 = __ldg((const int4*)(src) + q);
        int4 d4 = __ldg((const int4*)(dst) + q);
        int p;
        p = atomicAdd(&g_cur[d4.x], 1); if (p < MAXD) g_bkt[d4.x * MAXD + p] = s4.x;
        p = atomicAdd(&g_cur[d4.y], 1); if (p < MAXD) g_bkt[d4.y * MAXD + p] = s4.y;
        p = atomicAdd(&g_cur[d4.z], 1); if (p < MAXD) g_bkt[d4.z * MAXD + p] = s4.z;
        p = atomicAdd(&g_cur[d4.w], 1); if (p < MAXD) g_bkt[d4.w * MAXD + p] = s4.w;
    } else {
        for (int e = e0; e < E; e++) {
            int d = __ldg(&dst[e]);
            int p = atomicAdd(&g_cur[d], 1);
            if (p < MAXD) g_bkt[d * MAXD + p] = __ldg(&src[e]);
        }
    }
}

// W2: warp per node, float4-vectorized gather, 32 edges in flight (8 loads/lane).
// Writes X k-major: g_Xk[kq*NMAX + node].
__global__ void k_gather(const float* __restrict__ feat, int N)
{
    int t = threadIdx.x, lane = t & 31, w = t >> 5;
    int node = blockIdx.x * 8 + w;
    if (node >= N) return;
    int cnt = min(__ldg(&g_cur[node]), MAXD);
    int sub = lane >> 3;
    int ch  = lane & 7;

    float4 acc = make_float4(0.f, 0.f, 0.f, 0.f);
    const int* bkt = &g_bkt[node * MAXD];
    for (int base = 0; base < cnt; base += 32) {
        int i = base + sub;
        int s[8];
        #pragma unroll
        for (int k = 0; k < 8; k++)
            s[k] = (i + 4 * k < cnt) ? __ldg(&bkt[i + 4 * k]) : -1;
        #pragma unroll
        for (int k = 0; k < 8; k++) {
            if (s[k] >= 0) {
                float4 v = __ldg(reinterpret_cast<const float4*>(&feat[s[k] * 32]) + ch);
                acc.x += v.x; acc.y += v.y; acc.z += v.z; acc.w += v.w;
            }
        }
    }
    #pragma unroll
    for (int off = 16; off >= 8; off >>= 1) {
        acc.x += __shfl_xor_sync(0xffffffffu, acc.x, off);
        acc.y += __shfl_xor_sync(0xffffffffu, acc.y, off);
        acc.z += __shfl_xor_sync(0xffffffffu, acc.z, off);
        acc.w += __shfl_xor_sync(0xffffffffu, acc.w, off);
    }
    float degf = (float)cnt;
    if (lane < 8) {
        g_Xk[ch * NMAX + node] = acc;                     // F chunk, k-major
    } else if (lane < 16) {
        float4 fv = __ldg(reinterpret_cast<const float4*>(&feat[node * 32]) + ch);
        g_Xk[(8 + ch) * NMAX + node] = make_float4(degf * fv.x, degf * fv.y,
                                                   degf * fv.z, degf * fv.w);
    }
    if (lane == 0) g_degf[node] = degf;
}

// W3: persistent tiled GEMM (R11 config + conflict-free sW layout).
// 128 threads; thread = (tx 0..7 -> 8 outs, ty 0..15 -> nodes ty+n*16).
// sW layout: slots 0..7 = even o-quads, slots 8..15 = odd (128B-contiguous reads).
__global__ void __launch_bounds__(128) k_gemm(int N, int numTiles)
{
    __shared__ float4 sX[2048];   // [kq][128 nodes]
    __shared__ float4 sW[1024];   // permuted W[k][o]
    int t = threadIdx.x;
    for (int i = t; i < 1024; i += 128) {
        int r = i >> 4, slot = i & 15;
        int oq = (slot < 8) ? (2 * slot) : (2 * (slot - 8) + 1);
        sW[i] = __ldg(&((const float4*)g_W)[r * 16 + oq]);
    }

    int tx = t & 7, ty = t >> 3;
    float4 b1a = __ldg(&g_b1v[tx * 2]), b1b = __ldg(&g_b1v[tx * 2 + 1]);
    float4 b2a = __ldg(&g_b2v[tx * 2]), b2b = __ldg(&g_b2v[tx * 2 + 1]);
    int o = tx * 8;

    for (int tile = blockIdx.x; tile < numTiles; tile += gridDim.x) {
        int base = tile * 128;
        __syncthreads();    // prior tile's readers done before overwriting sX
        #pragma unroll
        for (int i = 0; i < 16; i++) {
            int idx = t + i * 128;           // 0..2047
            int kq = idx >> 7, n = idx & 127;
            int node = base + n;
            sX[idx] = (node < N) ? __ldg(&g_Xk[kq * NMAX + node])
                                 : make_float4(0.f, 0.f, 0.f, 0.f);
        }
        __syncthreads();

        float4 acc[8][2];
        #pragma unroll
        for (int n = 0; n < 8; n++) {
            acc[n][0] = make_float4(0.f, 0.f, 0.f, 0.f);
            acc[n][1] = make_float4(0.f, 0.f, 0.f, 0.f);
        }

        #pragma unroll
        for (int kk = 0; kk < 16; kk++) {
            float4 w0[4], w1[4];
            #pragma unroll
            for (int k4 = 0; k4 < 4; k4++) {
                int row = kk * 4 + k4;
                w0[k4] = sW[row * 16 + tx];       // conflict-free
                w1[k4] = sW[row * 16 + 8 + tx];
            }
            #pragma unroll
            for (int n = 0; n < 8; n++) {
                float4 xv = sX[kk * 128 + ty + n * 16];   // broadcast across tx
                float xs;
                #define FMA8(K4, XS) \
                    acc[n][0].x += (XS) * w0[K4].x; acc[n][0].y += (XS) * w0[K4].y; \
                    acc[n][0].z += (XS) * w0[K4].z; acc[n][0].w += (XS) * w0[K4].w; \
                    acc[n][1].x += (XS) * w1[K4].x; acc[n][1].y += (XS) * w1[K4].y; \
                    acc[n][1].z += (XS) * w1[K4].z; acc[n][1].w += (XS) * w1[K4].w;
                xs = xv.x; FMA8(0, xs);
                xs = xv.y; FMA8(1, xs);
                xs = xv.z; FMA8(2, xs);
                xs = xv.w; FMA8(3, xs);
                #undef FMA8
            }
        }

        #pragma unroll
        for (int n = 0; n < 8; n++) {
            int node = base + ty + n * 16;
            if (node >= N) continue;
            float dg = __ldg(&g_degf[node]);
            float4 y0 = make_float4(acc[n][0].x + dg * b1a.x + b2a.x,
                                    acc[n][0].y + dg * b1a.y + b2a.y,
                                    acc[n][0].z + dg * b1a.z + b2a.z,
                                    acc[n][0].w + dg * b1a.w + b2a.w);
            float4 y1 = make_float4(acc[n][1].x + dg * b1b.x + b2b.x,
                                    acc[n][1].y + dg * b1b.y + b2b.y,
                                    acc[n][1].z + dg * b1b.z + b2b.z,
                                    acc[n][1].w + dg * b1b.w + b2b.w);
            float* dstp = (o < 32) ? &g_src2[node * 32 + o] : &g_dst2[node * 32 + (o - 32)];
            ((float4*)dstp)[0] = y0;
            ((float4*)dstp)[1] = y1;
        }
    }
}

// W4: 4 threads/edge, 2 float4 each; idx loaded once per 4-lane group, shfl-broadcast.
// Streaming (__stwt) output writes keep src2/dst2 resident in L2.
// Also re-zeroes g_cur for the next launch (stream-ordered after k_gather).
__global__ void k_out(const int* __restrict__ src, const int* __restrict__ dst,
                      float4* __restrict__ out, int E, int N)
{
    int gt = blockIdx.x * blockDim.x + threadIdx.x;
    if (gt < N) g_cur[gt] = 0;
    if (gt >= E * 4) return;
    int e = gt >> 2;
    int lane = threadIdx.x & 31;
    int q = lane & 3;
    int s = 0, d = 0;
    if (q == 0) { s = __ldg(&src[e]); d = __ldg(&dst[e]); }
    s = __shfl_sync(0xffffffffu, s, lane & 28);
    d = __shfl_sync(0xffffffffu, d, lane & 28);
    const float4* ps = reinterpret_cast<const float4*>(&g_src2[s * 32]) + q * 2;
    const float4* pd = reinterpret_cast<const float4*>(&g_dst2[d * 32]) + q * 2;
    float4 a0 = __ldg(ps), a1 = __ldg(ps + 1);
    float4 b0 = __ldg(pd), b1 = __ldg(pd + 1);
    float4 r0 = make_float4(a0.x + b0.x, a0.y + b0.y, a0.z + b0.z, a0.w + b0.w);
    float4 r1 = make_float4(a1.x + b1.x, a1.y + b1.y, a1.z + b1.z, a1.w + b1.w);
    __stwt(&out[e * 8 + q * 2], r0);
    __stwt(&out[e * 8 + q * 2 + 1], r1);
}

extern "C" void kernel_launch(void* const* d_in, const int* in_sizes, int n_in,
                              void* d_out, int out_size)
{
    const float* feat = (const float*)d_in[0];
    const int*   src  = (const int*)d_in[1];
    const int*   dst  = (const int*)d_in[2];
    const float* Ws   = (const float*)d_in[3];
    const float* Wd   = (const float*)d_in[4];
    const float* bd   = (const float*)d_in[5];
    const float* Wr   = (const float*)d_in[6];
    const float* br   = (const float*)d_in[7];

    int N = in_sizes[0] / 32;
    int E = in_sizes[1];

    k_weights<<<1, 256>>>(Ws, Wd, bd, Wr, br);

    int buildBlocks = (E + 1023) / 1024;
    k_build<<<buildBlocks, 256>>>(src, dst, E);

    int gatherBlocks = (N + 7) / 8;
    k_gather<<<gatherBlocks, 256>>>(feat, N);

    int numTiles = (N + 127) / 128;
    int gemmBlocks = numTiles < 592 ? numTiles : 592;   // persistent, 4 blocks/SM
    k_gemm<<<gemmBlocks, 128>>>(N, numTiles);

    int outBlocks = (E * 4 + 255) / 256;
    k_out<<<outBlocks, 256>>>(src, dst, (float4*)d_out, E, N);
}

// round 15
// speedup vs baseline: 1.0490x; 1.0331x over previous
#include <cuda_runtime.h>
#include <cstdint>

#define NMAX 100000
#define EMAX 1600000
#define MAXD 64   // static bucket capacity; P(Poisson(16) > 64) ~ 1e-18

// scratch (static device globals — no allocation allowed)
__device__ float  g_src2[NMAX * 32];
__device__ float  g_dst2[NMAX * 32];
__device__ int    g_cur[NMAX];          // per-dst cursor == in-degree (zeroed by k_out)
__device__ int    g_bkt[NMAX * MAXD];   // src ids bucketed by dst
__device__ float4 g_Xk[16 * NMAX];      // K-MAJOR: [kq][node], kq<8: F, kq>=8: deg*fv
__device__ float  g_degf[NMAX];
__device__ float  g_W[64 * 64];         // W[k][o]: combined A1/A2/B1/B2 (k=in, o=out)
__device__ float4 g_b1v[16], g_b2v[16]; // bias: y[o] += deg*b1[o] + b2[o]

// W0 (fused): block 0 composes weights; blocks >=1 bucket-build (4 edges/thread, int4).
__global__ void __launch_bounds__(256) k_prep(const float* __restrict__ Ws,
                                              const float* __restrict__ Wd,
                                              const float* __restrict__ bd,
                                              const float* __restrict__ Wr,
                                              const float* __restrict__ br,
                                              const int* __restrict__ src,
                                              const int* __restrict__ dst, int E)
{
    if (blockIdx.x != 0) {
        int q = (blockIdx.x - 1) * blockDim.x + threadIdx.x;
        int e0 = q * 4;
        if (e0 + 3 < E) {
            int4 s4 = __ldg((const int4*)(src) + q);
            int4 d4 = __ldg((const int4*)(dst) + q);
            int p;
            p = atomicAdd(&g_cur[d4.x], 1); if (p < MAXD) g_bkt[d4.x * MAXD + p] = s4.x;
            p = atomicAdd(&g_cur[d4.y], 1); if (p < MAXD) g_bkt[d4.y * MAXD + p] = s4.y;
            p = atomicAdd(&g_cur[d4.z], 1); if (p < MAXD) g_bkt[d4.z * MAXD + p] = s4.z;
            p = atomicAdd(&g_cur[d4.w], 1); if (p < MAXD) g_bkt[d4.w * MAXD + p] = s4.w;
        } else {
            for (int e = e0; e < E; e++) {
                int d = __ldg(&dst[e]);
                int p = atomicAdd(&g_cur[d], 1);
                if (p < MAXD) g_bkt[d * MAXD + p] = __ldg(&src[e]);
            }
        }
        return;
    }
    // ---- weight composition path (single block) ----
    __shared__ float sWs[1024], sWd[1024], sWr[1024], sP[1024], sQ[1024];
    __shared__ float sp[32];
    int t = threadIdx.x;
    for (int i = t; i < 1024; i += 256) {
        sWs[i] = Ws[i]; sWd[i] = Wd[i]; sWr[i] = Wr[i];
    }
    __syncthreads();
    for (int i = t; i < 1024; i += 256) {
        int r = i >> 5, c = i & 31;
        float accP = 0.f, accQ = 0.f;
        #pragma unroll
        for (int k = 0; k < 32; k++) {
            float w = sWr[r * 32 + k];
            accP += w * sWs[k * 32 + c];
            accQ += w * sWd[k * 32 + c];
        }
        sP[i] = accP; sQ[i] = accQ;
    }
    if (t < 32) {
        float acc = 0.f;
        #pragma unroll
        for (int k = 0; k < 32; k++) acc += sWr[t * 32 + k] * bd[k];
        sp[t] = acc;
    }
    __syncthreads();
    for (int i = t; i < 1024; i += 256) {
        int r = i >> 5, c = i & 31;
        float a1 = 0.f, a2 = 0.f, b1 = 0.f, b2 = 0.f;
        #pragma unroll
        for (int k = 0; k < 32; k++) {
            float ws = sWs[r * 32 + k], wd = sWd[r * 32 + k];
            float pk = sP[k * 32 + c], qk = sQ[k * 32 + c];
            a1 += ws * pk; a2 += ws * qk;
            b1 += wd * pk; b2 += wd * qk;
        }
        g_W[c * 64 + r]               = a1;
        g_W[(c + 32) * 64 + r]        = a2;
        g_W[c * 64 + (r + 32)]        = b1;
        g_W[(c + 32) * 64 + (r + 32)] = b2;
    }
    if (t < 32) {
        float c1 = 0.f, c2 = 0.f, d1 = 0.f, d2 = 0.f;
        #pragma unroll
        for (int k = 0; k < 32; k++) {
            float ws = sWs[t * 32 + k], wd = sWd[t * 32 + k];
            c1 += ws * sp[k];  c2 += ws * br[k];
            d1 += wd * sp[k];  d2 += wd * br[k];
        }
        float* b1p = (float*)g_b1v;
        float* b2p = (float*)g_b2v;
        b1p[t] = c1;       b2p[t] = c2;
        b1p[t + 32] = d1;  b2p[t + 32] = d2 + bd[t];
    }
}

// W2: warp per node, float4-vectorized gather, 32 edges in flight (8 loads/lane).
// Writes X k-major: g_Xk[kq*NMAX + node].
__global__ void k_gather(const float* __restrict__ feat, int N)
{
    int t = threadIdx.x, lane = t & 31, w = t >> 5;
    int node = blockIdx.x * 8 + w;
    if (node >= N) return;
    int cnt = min(__ldg(&g_cur[node]), MAXD);
    int sub = lane >> 3;
    int ch  = lane & 7;

    float4 acc = make_float4(0.f, 0.f, 0.f, 0.f);
    const int* bkt = &g_bkt[node * MAXD];
    for (int base = 0; base < cnt; base += 32) {
        int i = base + sub;
        int s[8];
        #pragma unroll
        for (int k = 0; k < 8; k++)
            s[k] = (i + 4 * k < cnt) ? __ldg(&bkt[i + 4 * k]) : -1;
        #pragma unroll
        for (int k = 0; k < 8; k++) {
            if (s[k] >= 0) {
                float4 v = __ldg(reinterpret_cast<const float4*>(&feat[s[k] * 32]) + ch);
                acc.x += v.x; acc.y += v.y; acc.z += v.z; acc.w += v.w;
            }
        }
    }
    #pragma unroll
    for (int off = 16; off >= 8; off >>= 1) {
        acc.x += __shfl_xor_sync(0xffffffffu, acc.x, off);
        acc.y += __shfl_xor_sync(0xffffffffu, acc.y, off);
        acc.z += __shfl_xor_sync(0xffffffffu, acc.z, off);
        acc.w += __shfl_xor_sync(0xffffffffu, acc.w, off);
    }
    float degf = (float)cnt;
    if (lane < 8) {
        g_Xk[ch * NMAX + node] = acc;                     // F chunk, k-major
    } else if (lane < 16) {
        float4 fv = __ldg(reinterpret_cast<const float4*>(&feat[node * 32]) + ch);
        g_Xk[(8 + ch) * NMAX + node] = make_float4(degf * fv.x, degf * fv.y,
                                                   degf * fv.z, degf * fv.w);
    }
    if (lane == 0) g_degf[node] = degf;
}

// W3: persistent tiled GEMM, high-occupancy micro-tile.
// 256 threads; thread = (tx 0..15 -> out-quad tx, ty 0..15 -> nodes ty+n*16, n=0..7).
// 32 accumulator regs/thread -> ~3 blocks/SM resident.
__global__ void __launch_bounds__(256) k_gemm(int N, int numTiles)
{
    __shared__ float4 sX[2048];   // [kq][128 nodes]
    __shared__ float4 sW[1024];   // W[k][o], natural layout
    int t = threadIdx.x;
    for (int i = t; i < 1024; i += 256) sW[i] = __ldg(&((const float4*)g_W)[i]);

    int tx = t & 15, ty = t >> 4;
    float4 b1 = __ldg(&g_b1v[tx]);
    float4 b2 = __ldg(&g_b2v[tx]);
    int o = tx * 4;

    for (int tile = blockIdx.x; tile < numTiles; tile += gridDim.x) {
        int base = tile * 128;
        __syncthreads();    // prior tile's readers done before overwriting sX
        #pragma unroll
        for (int i = 0; i < 8; i++) {
            int idx = t + i * 256;           // 0..2047
            int kq = idx >> 7, n = idx & 127;
            int node = base + n;
            sX[idx] = (node < N) ? __ldg(&g_Xk[kq * NMAX + node])
                                 : make_float4(0.f, 0.f, 0.f, 0.f);
        }
        __syncthreads();

        float4 acc[8];
        #pragma unroll
        for (int n = 0; n < 8; n++) acc[n] = make_float4(0.f, 0.f, 0.f, 0.f);

        #pragma unroll
        for (int kk = 0; kk < 16; kk++) {
            float4 w0 = sW[(kk * 4 + 0) * 16 + tx];
            float4 w1 = sW[(kk * 4 + 1) * 16 + tx];
            float4 w2 = sW[(kk * 4 + 2) * 16 + tx];
            float4 w3 = sW[(kk * 4 + 3) * 16 + tx];
            #pragma unroll
            for (int n = 0; n < 8; n++) {
                float4 xv = sX[kk * 128 + ty + n * 16];   // broadcast
                acc[n].x += xv.x * w0.x + xv.y * w1.x + xv.z * w2.x + xv.w * w3.x;
                acc[n].y += xv.x * w0.y + xv.y * w1.y + xv.z * w2.y + xv.w * w3.y;
                acc[n].z += xv.x * w0.z + xv.y * w1.z + xv.z * w2.z + xv.w * w3.z;
                acc[n].w += xv.x * w0.w + xv.y * w1.w + xv.z * w2.w + xv.w * w3.w;
            }
        }

        #pragma unroll
        for (int n = 0; n < 8; n++) {
            int node = base + ty + n * 16;
            if (node >= N) continue;
            float dg = __ldg(&g_degf[node]);
            float4 y = make_float4(acc[n].x + dg * b1.x + b2.x,
                                   acc[n].y + dg * b1.y + b2.y,
                                   acc[n].z + dg * b1.z + b2.z,
                                   acc[n].w + dg * b1.w + b2.w);
            float* dstp = (o < 32) ? &g_src2[node * 32 + o] : &g_dst2[node * 32 + (o - 32)];
            *(float4*)dstp = y;
        }
    }
}

// W4: 4 threads/edge, 2 float4 each; idx loaded once per 4-lane group, shfl-broadcast.
// Streaming (__stwt) output writes keep src2/dst2 resident in L2.
// Also re-zeroes g_cur for the next launch (stream-ordered after k_gather).
__global__ void k_out(const int* __restrict__ src, const int* __restrict__ dst,
                      float4* __restrict__ out, int E, int N)
{
    int gt = blockIdx.x * blockDim.x + threadIdx.x;
    if (gt < N) g_cur[gt] = 0;
    if (gt >= E * 4) return;
    int e = gt >> 2;
    int lane = threadIdx.x & 31;
    int q = lane & 3;
    int s = 0, d = 0;
    if (q == 0) { s = __ldg(&src[e]); d = __ldg(&dst[e]); }
    s = __shfl_sync(0xffffffffu, s, lane & 28);
    d = __shfl_sync(0xffffffffu, d, lane & 28);
    const float4* ps = reinterpret_cast<const float4*>(&g_src2[s * 32]) + q * 2;
    const float4* pd = reinterpret_cast<const float4*>(&g_dst2[d * 32]) + q * 2;
    float4 a0 = __ldg(ps), a1 = __ldg(ps + 1);
    float4 b0 = __ldg(pd), b1 = __ldg(pd + 1);
    float4 r0 = make_float4(a0.x + b0.x, a0.y + b0.y, a0.z + b0.z, a0.w + b0.w);
    float4 r1 = make_float4(a1.x + b1.x, a1.y + b1.y, a1.z + b1.z, a1.w + b1.w);
    __stwt(&out[e * 8 + q * 2], r0);
    __stwt(&out[e * 8 + q * 2 + 1], r1);
}

extern "C" void kernel_launch(void* const* d_in, const int* in_sizes, int n_in,
                              void* d_out, int out_size)
{
    const float* feat = (const float*)d_in[0];
    const int*   src  = (const int*)d_in[1];
    const int*   dst  = (const int*)d_in[2];
    const float* Ws   = (const float*)d_in[3];
    const float* Wd   = (const float*)d_in[4];
    const float* bd   = (const float*)d_in[5];
    const float* Wr   = (const float*)d_in[6];
    const float* br   = (const float*)d_in[7];

    int N = in_sizes[0] / 32;
    int E = in_sizes[1];

    int buildBlocks = (E + 1023) / 1024;   // 4 edges/thread
    k_prep<<<1 + buildBlocks, 256>>>(Ws, Wd, bd, Wr, br, src, dst, E);

    int gatherBlocks = (N + 7) / 8;
    k_gather<<<gatherBlocks, 256>>>(feat, N);

    int numTiles = (N + 127) / 128;
    int gemmBlocks = numTiles < 444 ? numTiles : 444;   // persistent, ~3 blocks/SM
    k_gemm<<<gemmBlocks, 256>>>(N, numTiles);

    int outBlocks = (E * 4 + 255) / 256;
    k_out<<<outBlocks, 256>>>(src, dst, (float4*)d_out, E, N);
}

// round 16
// speedup vs baseline: 1.0546x; 1.0053x over previous
#include <cuda_runtime.h>
#include <cstdint>

#define NMAX 100000
#define EMAX 1600000
#define MAXD 64   // static bucket capacity; P(Poisson(16) > 64) ~ 1e-18

// scratch (static device globals — no allocation allowed)
__device__ float  g_src2[NMAX * 32];
__device__ float  g_dst2[NMAX * 32];
__device__ int    g_cur[NMAX];          // per-dst cursor == in-degree (zeroed by k_gemm)
__device__ int    g_bkt[NMAX * MAXD];   // src ids bucketed by dst
__device__ float4 g_Xk[16 * NMAX];      // K-MAJOR: [kq][node], kq<8: F, kq>=8: deg*fv
__device__ float  g_degf[NMAX];
__device__ float  g_W[64 * 64];         // W[k][o]: combined A1/A2/B1/B2 (k=in, o=out)
__device__ float4 g_b1v[16], g_b2v[16]; // bias: y[o] += deg*b1[o] + b2[o]

// W0 (fused): block 0 composes weights; blocks >=1 bucket-build (4 edges/thread, int4).
__global__ void __launch_bounds__(256) k_prep(const float* __restrict__ Ws,
                                              const float* __restrict__ Wd,
                                              const float* __restrict__ bd,
                                              const float* __restrict__ Wr,
                                              const float* __restrict__ br,
                                              const int* __restrict__ src,
                                              const int* __restrict__ dst, int E)
{
    if (blockIdx.x != 0) {
        int q = (blockIdx.x - 1) * blockDim.x + threadIdx.x;
        int e0 = q * 4;
        if (e0 + 3 < E) {
            int4 s4 = __ldg((const int4*)(src) + q);
            int4 d4 = __ldg((const int4*)(dst) + q);
            int p;
            p = atomicAdd(&g_cur[d4.x], 1); if (p < MAXD) g_bkt[d4.x * MAXD + p] = s4.x;
            p = atomicAdd(&g_cur[d4.y], 1); if (p < MAXD) g_bkt[d4.y * MAXD + p] = s4.y;
            p = atomicAdd(&g_cur[d4.z], 1); if (p < MAXD) g_bkt[d4.z * MAXD + p] = s4.z;
            p = atomicAdd(&g_cur[d4.w], 1); if (p < MAXD) g_bkt[d4.w * MAXD + p] = s4.w;
        } else {
            for (int e = e0; e < E; e++) {
                int d = __ldg(&dst[e]);
                int p = atomicAdd(&g_cur[d], 1);
                if (p < MAXD) g_bkt[d * MAXD + p] = __ldg(&src[e]);
            }
        }
        return;
    }
    // ---- weight composition path (single block) ----
    __shared__ float sWs[1024], sWd[1024], sWr[1024], sP[1024], sQ[1024];
    __shared__ float sp[32];
    int t = threadIdx.x;
    for (int i = t; i < 1024; i += 256) {
        sWs[i] = Ws[i]; sWd[i] = Wd[i]; sWr[i] = Wr[i];
    }
    __syncthreads();
    for (int i = t; i < 1024; i += 256) {
        int r = i >> 5, c = i & 31;
        float accP = 0.f, accQ = 0.f;
        #pragma unroll
        for (int k = 0; k < 32; k++) {
            float w = sWr[r * 32 + k];
            accP += w * sWs[k * 32 + c];
            accQ += w * sWd[k * 32 + c];
        }
        sP[i] = accP; sQ[i] = accQ;
    }
    if (t < 32) {
        float acc = 0.f;
        #pragma unroll
        for (int k = 0; k < 32; k++) acc += sWr[t * 32 + k] * bd[k];
        sp[t] = acc;
    }
    __syncthreads();
    for (int i = t; i < 1024; i += 256) {
        int r = i >> 5, c = i & 31;
        float a1 = 0.f, a2 = 0.f, b1 = 0.f, b2 = 0.f;
        #pragma unroll
        for (int k = 0; k < 32; k++) {
            float ws = sWs[r * 32 + k], wd = sWd[r * 32 + k];
            float pk = sP[k * 32 + c], qk = sQ[k * 32 + c];
            a1 += ws * pk; a2 += ws * qk;
            b1 += wd * pk; b2 += wd * qk;
        }
        g_W[c * 64 + r]               = a1;
        g_W[(c + 32) * 64 + r]        = a2;
        g_W[c * 64 + (r + 32)]        = b1;
        g_W[(c + 32) * 64 + (r + 32)] = b2;
    }
    if (t < 32) {
        float c1 = 0.f, c2 = 0.f, d1 = 0.f, d2 = 0.f;
        #pragma unroll
        for (int k = 0; k < 32; k++) {
            float ws = sWs[t * 32 + k], wd = sWd[t * 32 + k];
            c1 += ws * sp[k];  c2 += ws * br[k];
            d1 += wd * sp[k];  d2 += wd * br[k];
        }
        float* b1p = (float*)g_b1v;
        float* b2p = (float*)g_b2v;
        b1p[t] = c1;       b2p[t] = c2;
        b1p[t + 32] = d1;  b2p[t + 32] = d2 + bd[t];
    }
}

// W2: warp per node, float4-vectorized gather, 32 edges in flight (8 loads/lane).
// Writes X k-major: g_Xk[kq*NMAX + node].
__global__ void k_gather(const float* __restrict__ feat, int N)
{
    int t = threadIdx.x, lane = t & 31, w = t >> 5;
    int node = blockIdx.x * 8 + w;
    if (node >= N) return;
    int cnt = min(__ldg(&g_cur[node]), MAXD);
    int sub = lane >> 3;
    int ch  = lane & 7;

    float4 acc = make_float4(0.f, 0.f, 0.f, 0.f);
    const int* bkt = &g_bkt[node * MAXD];
    for (int base = 0; base < cnt; base += 32) {
        int i = base + sub;
        int s[8];
        #pragma unroll
        for (int k = 0; k < 8; k++)
            s[k] = (i + 4 * k < cnt) ? __ldg(&bkt[i + 4 * k]) : -1;
        #pragma unroll
        for (int k = 0; k < 8; k++) {
            if (s[k] >= 0) {
                float4 v = __ldg(reinterpret_cast<const float4*>(&feat[s[k] * 32]) + ch);
                acc.x += v.x; acc.y += v.y; acc.z += v.z; acc.w += v.w;
            }
        }
    }
    #pragma unroll
    for (int off = 16; off >= 8; off >>= 1) {
        acc.x += __shfl_xor_sync(0xffffffffu, acc.x, off);
        acc.y += __shfl_xor_sync(0xffffffffu, acc.y, off);
        acc.z += __shfl_xor_sync(0xffffffffu, acc.z, off);
        acc.w += __shfl_xor_sync(0xffffffffu, acc.w, off);
    }
    float degf = (float)cnt;
    if (lane < 8) {
        g_Xk[ch * NMAX + node] = acc;                     // F chunk, k-major
    } else if (lane < 16) {
        float4 fv = __ldg(reinterpret_cast<const float4*>(&feat[node * 32]) + ch);
        g_Xk[(8 + ch) * NMAX + node] = make_float4(degf * fv.x, degf * fv.y,
                                                   degf * fv.z, degf * fv.w);
    }
    if (lane == 0) g_degf[node] = degf;
}

// W3: persistent tiled GEMM, EXACTLY 2 tiles per block (perfect balance).
// 256 threads; thread = (tx 0..15 -> out-quad tx, ty 0..15 -> nodes ty+n*16, n=0..7).
// Also re-zeroes g_cur for the next launch (stream-ordered: gather already read it).
__global__ void __launch_bounds__(256) k_gemm(int N, int numTiles)
{
    __shared__ float4 sX[2048];   // [kq][128 nodes]
    __shared__ float4 sW[1024];   // W[k][o], natural layout
    int t = threadIdx.x;
    for (int i = t; i < 1024; i += 256) sW[i] = __ldg(&((const float4*)g_W)[i]);

    int gid = blockIdx.x * 256 + t;        // re-zero cursor (grid*256 >= N)
    if (gid < N) g_cur[gid] = 0;

    int tx = t & 15, ty = t >> 4;
    float4 b1 = __ldg(&g_b1v[tx]);
    float4 b2 = __ldg(&g_b2v[tx]);
    int o = tx * 4;

    for (int tile = blockIdx.x; tile < numTiles; tile += gridDim.x) {
        int base = tile * 128;
        __syncthreads();    // prior tile's readers done before overwriting sX
        #pragma unroll
        for (int i = 0; i < 8; i++) {
            int idx = t + i * 256;           // 0..2047
            int kq = idx >> 7, n = idx & 127;
            int node = base + n;
            sX[idx] = (node < N) ? __ldg(&g_Xk[kq * NMAX + node])
                                 : make_float4(0.f, 0.f, 0.f, 0.f);
        }
        __syncthreads();

        float4 acc[8];
        #pragma unroll
        for (int n = 0; n < 8; n++) acc[n] = make_float4(0.f, 0.f, 0.f, 0.f);

        #pragma unroll
        for (int kk = 0; kk < 16; kk++) {
            float4 w0 = sW[(kk * 4 + 0) * 16 + tx];
            float4 w1 = sW[(kk * 4 + 1) * 16 + tx];
            float4 w2 = sW[(kk * 4 + 2) * 16 + tx];
            float4 w3 = sW[(kk * 4 + 3) * 16 + tx];
            #pragma unroll
            for (int n = 0; n < 8; n++) {
                float4 xv = sX[kk * 128 + ty + n * 16];   // broadcast
                acc[n].x += xv.x * w0.x + xv.y * w1.x + xv.z * w2.x + xv.w * w3.x;
                acc[n].y += xv.x * w0.y + xv.y * w1.y + xv.z * w2.y + xv.w * w3.y;
                acc[n].z += xv.x * w0.z + xv.y * w1.z + xv.z * w2.z + xv.w * w3.z;
                acc[n].w += xv.x * w0.w + xv.y * w1.w + xv.z * w2.w + xv.w * w3.w;
            }
        }

        #pragma unroll
        for (int n = 0; n < 8; n++) {
            int node = base + ty + n * 16;
            if (node >= N) continue;
            float dg = __ldg(&g_degf[node]);
            float4 y = make_float4(acc[n].x + dg * b1.x + b2.x,
                                   acc[n].y + dg * b1.y + b2.y,
                                   acc[n].z + dg * b1.z + b2.z,
                                   acc[n].w + dg * b1.w + b2.w);
            float* dstp = (o < 32) ? &g_src2[node * 32 + o] : &g_dst2[node * 32 + (o - 32)];
            *(float4*)dstp = y;
        }
    }
}

// W4: 4 threads/edge, 2 float4 each; idx loaded once per 4-lane group, shfl-broadcast.
// Streaming (__stwt) output writes keep src2/dst2 resident in L2.
__global__ void k_out(const int* __restrict__ src, const int* __restrict__ dst,
                      float4* __restrict__ out, int E)
{
    int gt = blockIdx.x * blockDim.x + threadIdx.x;
    if (gt >= E * 4) return;
    int e = gt >> 2;
    int lane = threadIdx.x & 31;
    int q = lane & 3;
    int s = 0, d = 0;
    if (q == 0) { s = __ldg(&src[e]); d = __ldg(&dst[e]); }
    s = __shfl_sync(0xffffffffu, s, lane & 28);
    d = __shfl_sync(0xffffffffu, d, lane & 28);
    const float4* ps = reinterpret_cast<const float4*>(&g_src2[s * 32]) + q * 2;
    const float4* pd = reinterpret_cast<const float4*>(&g_dst2[d * 32]) + q * 2;
    float4 a0 = __ldg(ps), a1 = __ldg(ps + 1);
    float4 b0 = __ldg(pd), b1 = __ldg(pd + 1);
    float4 r0 = make_float4(a0.x + b0.x, a0.y + b0.y, a0.z + b0.z, a0.w + b0.w);
    float4 r1 = make_float4(a1.x + b1.x, a1.y + b1.y, a1.z + b1.z, a1.w + b1.w);
    __stwt(&out[e * 8 + q * 2], r0);
    __stwt(&out[e * 8 + q * 2 + 1], r1);
}

extern "C" void kernel_launch(void* const* d_in, const int* in_sizes, int n_in,
                              void* d_out, int out_size)
{
    const float* feat = (const float*)d_in[0];
    const int*   src  = (const int*)d_in[1];
    const int*   dst  = (const int*)d_in[2];
    const float* Ws   = (const float*)d_in[3];
    const float* Wd   = (const float*)d_in[4];
    const float* bd   = (const float*)d_in[5];
    const float* Wr   = (const float*)d_in[6];
    const float* br   = (const float*)d_in[7];

    int N = in_sizes[0] / 32;
    int E = in_sizes[1];

    int buildBlocks = (E + 1023) / 1024;   // 4 edges/thread
    k_prep<<<1 + buildBlocks, 256>>>(Ws, Wd, bd, Wr, br, src, dst, E);

    int gatherBlocks = (N + 7) / 8;
    k_gather<<<gatherBlocks, 256>>>(feat, N);

    int numTiles = (N + 127) / 128;
    int gemmBlocks = (numTiles + 1) / 2;   // exactly 2 tiles per block (782 -> 391)
    k_gemm<<<gemmBlocks, 256>>>(N, numTiles);

    int outBlocks = (E * 4 + 255) / 256;
    k_out<<<outBlocks, 256>>>(src, dst, (float4*)d_out, E);
}